// round 2
// baseline (speedup 1.0000x reference)
#include <cuda_runtime.h>
#include <math.h>

// ---------------------------------------------------------------------------
// NISQ classifier via Pauli-transfer-matrix simulation.
//
// State: c[p], p is 10 base-4 digits (one per "slot"), c_p = tr(P_p rho).
// Qubit q -> slot s via SLOT_OF_Q[]; matrix-index bit of qubit q is (9-q).
// ---------------------------------------------------------------------------

#define NSTATE (1 << 20)

__device__ float g_c[NSTATE];          // PTM state vector (4 MB)
__device__ float g_M[3][10][16];       // fused per-(layer,qubit) 4x4 PTM ops
__device__ float g_N2[3];              // post-CNOT per-wire noise: aN, zN, gN

// qubit -> slot assignment (chosen for tile locality/coalescing)
// q:      0  1  2  3  4  5  6  7  8  9
// slot:   2  3  4  5  1  6  7  8  0  9

// ---------------------------------------------------------------------------
// Prep: build fused 4x4 PTM ops from circuit weights (one tiny block).
// M = P_phase * P_amp * P_depol1 * P_rot
// ---------------------------------------------------------------------------
__global__ void prep_kernel(const float* __restrict__ wts /* [3][10][3] */) {
    int t = threadIdx.x;
    const double gamma = -expm1(-1e-7 / 0.05);   // P_AMP
    const double gph   = -expm1(-1e-7 / 0.07);   // P_PHASE
    const double c1 = 1.0 - 4.0 * 0.001 / 3.0;   // depol1 factor
    const double c2 = 1.0 - 4.0 * 0.01 / 3.0;    // depol2 factor
    const double sq = sqrt((1.0 - gamma) * (1.0 - gph));

    if (t == 0) {
        g_N2[0] = (float)(sq * c2);              // aN (X,Y damp)
        g_N2[1] = (float)((1.0 - gamma) * c2);   // zN (Z->Z)
        g_N2[2] = (float)gamma;                  // gN (I->Z feed)
    }
    if (t < 30) {
        int l = t / 10, q = t % 10;
        float phi = wts[(l * 10 + q) * 3 + 0];
        float th  = wts[(l * 10 + q) * 3 + 1];
        float om  = wts[(l * 10 + q) * 3 + 2];
        // R3 = Rz(om) * Ry(th) * Rz(phi)  (SO(3) action of qml.Rot)
        float cphi = cosf(phi), sphi = sinf(phi);
        float cth  = cosf(th),  sth  = sinf(th);
        float com  = cosf(om),  som  = sinf(om);
        float A[9]  = {com, -som, 0.f,  som, com, 0.f,  0.f, 0.f, 1.f};
        float Bm[9] = {cth, 0.f, sth,   0.f, 1.f, 0.f,  -sth, 0.f, cth};
        float C[9]  = {cphi, -sphi, 0.f, sphi, cphi, 0.f, 0.f, 0.f, 1.f};
        float AB[9], R[9];
        for (int i = 0; i < 3; i++)
            for (int j = 0; j < 3; j++) {
                float s = 0.f;
                for (int k = 0; k < 3; k++) s += A[i*3+k] * Bm[k*3+j];
                AB[i*3+j] = s;
            }
        for (int i = 0; i < 3; i++)
            for (int j = 0; j < 3; j++) {
                float s = 0.f;
                for (int k = 0; k < 3; k++) s += AB[i*3+k] * C[k*3+j];
                R[i*3+j] = s;
            }
        float a1 = (float)(sq * c1);
        float z1 = (float)((1.0 - gamma) * c1);
        float g1 = (float)gamma;
        float* M = g_M[l][q];
        M[0]  = 1.f; M[1]  = 0.f;       M[2]  = 0.f;       M[3]  = 0.f;
        M[4]  = 0.f; M[5]  = a1 * R[0]; M[6]  = a1 * R[1]; M[7]  = a1 * R[2];
        M[8]  = 0.f; M[9]  = a1 * R[3]; M[10] = a1 * R[4]; M[11] = a1 * R[5];
        M[12] = g1;  M[13] = z1 * R[6]; M[14] = z1 * R[7]; M[15] = z1 * R[8];
    }
}

// ---------------------------------------------------------------------------
// Tile ops on a 4096-float shared tile (12 bits = 6 local slots).
// ---------------------------------------------------------------------------
__device__ __forceinline__ void apply1(float* t, const float* __restrict__ M, int pos) {
    int sh = 2 * pos;
    unsigned mlo = (1u << sh) - 1u;
    float m5 = M[5], m6 = M[6], m7 = M[7];
    float m9 = M[9], m10 = M[10], m11 = M[11];
    float m12 = M[12], m13 = M[13], m14 = M[14], m15 = M[15];
    for (unsigned g = threadIdx.x; g < 1024; g += blockDim.x) {
        unsigned base = (g & mlo) | ((g & ~mlo) << 2);
        float v0 = t[base];
        float v1 = t[base + (1u << sh)];
        float v2 = t[base + (2u << sh)];
        float v3 = t[base + (3u << sh)];
        // row I is [1,0,0,0]: v0 unchanged
        t[base + (1u << sh)] = m5 * v1 + m6 * v2 + m7 * v3;
        t[base + (2u << sh)] = m9 * v1 + m10 * v2 + m11 * v3;
        t[base + (3u << sh)] = m12 * v0 + m13 * v1 + m14 * v2 + m15 * v3;
    }
}

// fused CNOT step: signed Pauli permutation then per-wire noise N (aN,zN,gN)
__device__ __forceinline__ void applyCNOT(float* t, int pc, int pt,
                                          float aN, float zN, float gN) {
    int sc = 2 * pc, st = 2 * pt;
    int plo = (sc < st) ? sc : st;
    int phi_ = (sc < st) ? st : sc;
    int midw = phi_ - plo - 2;
    for (unsigned g = threadIdx.x; g < 256; g += blockDim.x) {
        unsigned lo   = g & ((1u << plo) - 1u);
        unsigned rest = g >> plo;
        unsigned mid  = rest & ((1u << midw) - 1u);
        unsigned hi   = rest >> midw;
        unsigned base = lo | (mid << (plo + 2)) | (hi << (phi_ + 2));
        float v[16];
#pragma unroll
        for (int dc = 0; dc < 4; dc++)
#pragma unroll
            for (int dt = 0; dt < 4; dt++)
                v[dc * 4 + dt] = t[base + (dc << sc) + (dt << st)];
        // CNOT PTM: out[i] = sgn[i] * in[tbl[i]], i = 4*control + target
        const int tbl[16] = {0, 1, 14, 15, 5, 4, 11, 10, 9, 8, 7, 6, 12, 13, 2, 3};
        float w_[16];
#pragma unroll
        for (int i = 0; i < 16; i++) w_[i] = v[tbl[i]];
        w_[7]  = -w_[7];   // XZ <- -YY
        w_[10] = -w_[10];  // YY <- -XZ
        // noise on control digit
#pragma unroll
        for (int dt = 0; dt < 4; dt++) {
            float u0 = w_[0 + dt], u1 = w_[4 + dt], u2 = w_[8 + dt], u3 = w_[12 + dt];
            w_[4 + dt]  = aN * u1;
            w_[8 + dt]  = aN * u2;
            w_[12 + dt] = gN * u0 + zN * u3;
        }
        // noise on target digit
#pragma unroll
        for (int dc = 0; dc < 4; dc++) {
            float u0 = w_[dc * 4 + 0], u1 = w_[dc * 4 + 1];
            float u2 = w_[dc * 4 + 2], u3 = w_[dc * 4 + 3];
            w_[dc * 4 + 1] = aN * u1;
            w_[dc * 4 + 2] = aN * u2;
            w_[dc * 4 + 3] = gN * u0 + zN * u3;
        }
#pragma unroll
        for (int dc = 0; dc < 4; dc++)
#pragma unroll
            for (int dt = 0; dt < 4; dt++)
                t[base + (dc << sc) + (dt << st)] = w_[dc * 4 + dt];
    }
}

// ---------------------------------------------------------------------------
// Sim kernel: 256 blocks x 256 threads, 4096-elem tile per block, in-place.
// kind 0: local slots {0,1,2,3,4,5}   ops: M q0..q4, CNOT(q0,q1)..(q3,q4)
// kind 1: local slots {0,1,2,6,7,8}   ops: M q4..q8? no: M q5..q8 handled here
//         (M[l][4] already applied in kind 0 pass of same layer? NO —
//          M[l][4] must run exactly once; it runs in kind 0.)
// kind 2: local slots {0,1,2,3,4,9}   ops: M q9, CNOT(q8,q9), CNOT(q9,q0)
// ---------------------------------------------------------------------------
__global__ __launch_bounds__(256) void sim_kernel(int kind, int layer, int do_init) {
    __shared__ float t[4096];
    unsigned blk = blockIdx.x;

    // global index for tile element u
    auto gidx = [&](unsigned u) -> unsigned {
        if (kind == 0) {
            return u | (blk << 12);
        } else if (kind == 1) {
            return (u & 63u) | ((blk & 63u) << 6) | ((u >> 6) << 12) | ((blk >> 6) << 18);
        } else {
            return (u & 1023u) | (blk << 10) | ((u >> 10) << 18);
        }
    };

    if (do_init) {
        for (unsigned u = threadIdx.x; u < 4096; u += blockDim.x) {
            unsigned p = gidx(u);
            // initial |0..0><0..0|: c_p = 1 iff every base-4 digit is I(0) or Z(3)
            t[u] = ((((p >> 1) ^ p) & 0x55555u) == 0u) ? 1.0f : 0.0f;
        }
    } else {
        for (unsigned u = threadIdx.x; u < 4096; u += blockDim.x)
            t[u] = g_c[gidx(u)];
    }
    __syncthreads();

    float aN = g_N2[0], zN = g_N2[1], gN = g_N2[2];
    int l = layer;

    if (kind == 0) {
        // qubits 0..4 at local positions: q0->2 q1->3 q2->4 q3->5 q4->1
        apply1(t, g_M[l][0], 2); __syncthreads();
        apply1(t, g_M[l][1], 3); __syncthreads();
        apply1(t, g_M[l][2], 4); __syncthreads();
        apply1(t, g_M[l][3], 5); __syncthreads();
        apply1(t, g_M[l][4], 1); __syncthreads();
        applyCNOT(t, 2, 3, aN, zN, gN); __syncthreads();  // CNOT(q0,q1)
        applyCNOT(t, 3, 4, aN, zN, gN); __syncthreads();  // CNOT(q1,q2)
        applyCNOT(t, 4, 5, aN, zN, gN); __syncthreads();  // CNOT(q2,q3)
        applyCNOT(t, 5, 1, aN, zN, gN); __syncthreads();  // CNOT(q3,q4)
    } else if (kind == 1) {
        // local slots [0,1,2,6,7,8] -> pos [0..5]; qubits: q4->pos1 q5->pos3
        // q6->pos4 q7->pos5 q8->pos0
        apply1(t, g_M[l][5], 3); __syncthreads();
        apply1(t, g_M[l][6], 4); __syncthreads();
        apply1(t, g_M[l][7], 5); __syncthreads();
        apply1(t, g_M[l][8], 0); __syncthreads();
        applyCNOT(t, 1, 3, aN, zN, gN); __syncthreads();  // CNOT(q4,q5)
        applyCNOT(t, 3, 4, aN, zN, gN); __syncthreads();  // CNOT(q5,q6)
        applyCNOT(t, 4, 5, aN, zN, gN); __syncthreads();  // CNOT(q6,q7)
        applyCNOT(t, 5, 0, aN, zN, gN); __syncthreads();  // CNOT(q7,q8)
    } else {
        // local slots [0,1,2,3,4,9] -> q8->pos0, q9->pos5, q0->pos2
        apply1(t, g_M[l][9], 5); __syncthreads();
        applyCNOT(t, 0, 5, aN, zN, gN); __syncthreads();  // CNOT(q8,q9)
        applyCNOT(t, 5, 2, aN, zN, gN); __syncthreads();  // CNOT(q9,q0)
    }

    for (unsigned u = threadIdx.x; u < 4096; u += blockDim.x)
        g_c[gidx(u)] = t[u];
}

// ---------------------------------------------------------------------------
// Logits: one block per batch row.
// logit[b] = sum_m x[m]*( sum_j cA[j]*x[m^(1<<j)] + cB[j]*(+-x[m]) )
// where j = 9-q is the matrix bit of qubit q.
// ---------------------------------------------------------------------------
__global__ __launch_bounds__(256) void logits_kernel(
    const float* __restrict__ x, const float* __restrict__ bvec,
    const float* __restrict__ w, float* __restrict__ out) {
    __shared__ float xs[1024];
    __shared__ float cA[10], cB[10];
    __shared__ float red[8];
    int row = blockIdx.x, tid = threadIdx.x;

    for (int m = tid; m < 1024; m += 256)
        xs[m] = x[row * 1024 + m] + bvec[m];

    if (tid < 10) {
        const int slot_of_q[10] = {2, 3, 4, 5, 1, 6, 7, 8, 0, 9};
        int q = tid;
        int j = 9 - q;
        int s2 = 2 * slot_of_q[q];
        cA[j] = w[2 * q] * g_c[1u << s2];
        cB[j] = w[2 * q + 1] * 0.96f * g_c[3u << s2];   // readout bitflip: 1-2*0.02
    }
    __syncthreads();

    float acc = 0.f;
    for (int m = tid; m < 1024; m += 256) {
        float xm = xs[m];
        float s = 0.f;
#pragma unroll
        for (int j = 0; j < 10; j++) {
            s += cA[j] * xs[m ^ (1 << j)];
            s += cB[j] * (((m >> j) & 1) ? -xm : xm);
        }
        acc += xm * s;
    }
#pragma unroll
    for (int off = 16; off > 0; off >>= 1)
        acc += __shfl_down_sync(0xFFFFFFFFu, acc, off);
    if ((tid & 31) == 0) red[tid >> 5] = acc;
    __syncthreads();
    if (tid < 8) {
        float a = red[tid];
#pragma unroll
        for (int off = 4; off > 0; off >>= 1)
            a += __shfl_down_sync(0xFFu, a, off);
        if (tid == 0) out[row] = 1.f / (1.f + expf(-a));
    }
}

// ---------------------------------------------------------------------------
extern "C" void kernel_launch(void* const* d_in, const int* in_sizes, int n_in,
                              void* d_out, int out_size) {
    const float* x = nullptr;
    const float* bv = nullptr;
    const float* w = nullptr;
    const float* cw = nullptr;
    for (int i = 0; i < n_in; i++) {
        switch (in_sizes[i]) {
            case 2048 * 1024: x = (const float*)d_in[i]; break;
            case 1024:        bv = (const float*)d_in[i]; break;
            case 20:          w = (const float*)d_in[i]; break;
            case 90:          cw = (const float*)d_in[i]; break;
            default: break;  // P_tensor (20971520) unused
        }
    }

    prep_kernel<<<1, 32>>>(cw);
    for (int l = 0; l < 3; l++) {
        sim_kernel<<<256, 256>>>(0, l, l == 0 ? 1 : 0);
        sim_kernel<<<256, 256>>>(1, l, 0);
        sim_kernel<<<256, 256>>>(2, l, 0);
    }
    logits_kernel<<<2048, 256>>>(x, bv, w, (float*)d_out);
}

// round 3
// speedup vs baseline: 1.4293x; 1.4293x over previous
#include <cuda_runtime.h>
#include <math.h>

// ---------------------------------------------------------------------------
// NISQ classifier via Pauli-transfer-matrix simulation (fused-pass version).
// State c[p], p = 10 base-4 digits (slots). qubit q -> slot via
//   q:    0  1  2  3  4  5  6  7  8  9
//   slot: 2  3  4  5  1  6  7  8  0  9
// ---------------------------------------------------------------------------

#define NSTATE (1 << 20)
__device__ float g_c[NSTATE];   // PTM state vector (4 MB)

// Build fused single-qubit PTM op: M = phase*amp*depol1*Rot  (4x4, row I = e0)
__device__ __forceinline__ void build_M(float phi, float th, float om, float* M) {
    float cphi = cosf(phi), sphi = sinf(phi);
    float cth  = cosf(th),  sth  = sinf(th);
    float com  = cosf(om),  som  = sinf(om);
    float A[9]  = {com, -som, 0.f,  som, com, 0.f,  0.f, 0.f, 1.f};
    float Bm[9] = {cth, 0.f, sth,   0.f, 1.f, 0.f,  -sth, 0.f, cth};
    float C[9]  = {cphi, -sphi, 0.f, sphi, cphi, 0.f, 0.f, 0.f, 1.f};
    float AB[9], R[9];
#pragma unroll
    for (int i = 0; i < 3; i++)
#pragma unroll
        for (int j = 0; j < 3; j++) {
            float s = 0.f;
#pragma unroll
            for (int k = 0; k < 3; k++) s += A[i*3+k] * Bm[k*3+j];
            AB[i*3+j] = s;
        }
#pragma unroll
    for (int i = 0; i < 3; i++)
#pragma unroll
        for (int j = 0; j < 3; j++) {
            float s = 0.f;
#pragma unroll
            for (int k = 0; k < 3; k++) s += AB[i*3+k] * C[k*3+j];
            R[i*3+j] = s;
        }
    const float gamma = -expm1f(-1e-7f / 0.05f);
    const float gph   = -expm1f(-1e-7f / 0.07f);
    const float c1    = 1.0f - 4.0f * 0.001f / 3.0f;
    float sq = sqrtf((1.f - gamma) * (1.f - gph));
    float a1 = sq * c1, z1 = (1.f - gamma) * c1, g1 = gamma;
    M[0]  = 1.f; M[1]  = 0.f;       M[2]  = 0.f;       M[3]  = 0.f;
    M[4]  = 0.f; M[5]  = a1 * R[0]; M[6]  = a1 * R[1]; M[7]  = a1 * R[2];
    M[8]  = 0.f; M[9]  = a1 * R[3]; M[10] = a1 * R[4]; M[11] = a1 * R[5];
    M[12] = g1;  M[13] = z1 * R[6]; M[14] = z1 * R[7]; M[15] = z1 * R[8];
}

// Fused pass: (optional) single ops on control/target digits, then
// CNOT signed-permutation + per-wire 2-qubit noise. One 16-elem block/thread.
template<int PC, int PT, bool HASMT, bool HASMC>
__device__ __forceinline__ void pass(float* t,
                                     const float* __restrict__ MT,
                                     const float* __restrict__ MC,
                                     float aN, float zN, float gN) {
    constexpr int sc = 2 * PC, st = 2 * PT;
    constexpr int plo  = (sc < st) ? sc : st;
    constexpr int phi_ = (sc < st) ? st : sc;
    constexpr int midw = phi_ - plo - 2;
    unsigned g    = threadIdx.x;                 // 256 groups, 256 threads
    unsigned lo   = g & ((1u << plo) - 1u);
    unsigned rest = g >> plo;
    unsigned mid  = rest & ((1u << midw) - 1u);
    unsigned hi   = rest >> midw;
    unsigned base = lo | (mid << (plo + 2)) | (hi << (phi_ + 2));

    float v[16];
#pragma unroll
    for (int dc = 0; dc < 4; dc++)
#pragma unroll
        for (int dt = 0; dt < 4; dt++)
            v[dc * 4 + dt] = t[base + (dc << sc) + (dt << st)];

    if (HASMT) {   // single-qubit op on target digit
#pragma unroll
        for (int dc = 0; dc < 4; dc++) {
            float v0 = v[dc*4+0], v1 = v[dc*4+1], v2 = v[dc*4+2], v3 = v[dc*4+3];
            v[dc*4+1] = MT[5]  * v1 + MT[6]  * v2 + MT[7]  * v3;
            v[dc*4+2] = MT[9]  * v1 + MT[10] * v2 + MT[11] * v3;
            v[dc*4+3] = MT[12] * v0 + MT[13] * v1 + MT[14] * v2 + MT[15] * v3;
        }
    }
    if (HASMC) {   // single-qubit op on control digit
#pragma unroll
        for (int dt = 0; dt < 4; dt++) {
            float v0 = v[0+dt], v1 = v[4+dt], v2 = v[8+dt], v3 = v[12+dt];
            v[4 + dt]  = MC[5]  * v1 + MC[6]  * v2 + MC[7]  * v3;
            v[8 + dt]  = MC[9]  * v1 + MC[10] * v2 + MC[11] * v3;
            v[12 + dt] = MC[12] * v0 + MC[13] * v1 + MC[14] * v2 + MC[15] * v3;
        }
    }

    // CNOT PTM: out[i] = sgn[i] * in[tbl[i]], i = 4*control + target
    const int tbl[16] = {0, 1, 14, 15, 5, 4, 11, 10, 9, 8, 7, 6, 12, 13, 2, 3};
    float w_[16];
#pragma unroll
    for (int i = 0; i < 16; i++) w_[i] = v[tbl[i]];
    w_[7]  = -w_[7];
    w_[10] = -w_[10];
    // post-CNOT noise, control digit
#pragma unroll
    for (int dt = 0; dt < 4; dt++) {
        float u0 = w_[0+dt], u1 = w_[4+dt], u2 = w_[8+dt], u3 = w_[12+dt];
        w_[4 + dt]  = aN * u1;
        w_[8 + dt]  = aN * u2;
        w_[12 + dt] = gN * u0 + zN * u3;
    }
    // post-CNOT noise, target digit
#pragma unroll
    for (int dc = 0; dc < 4; dc++) {
        float u0 = w_[dc*4+0], u1 = w_[dc*4+1], u2 = w_[dc*4+2], u3 = w_[dc*4+3];
        w_[dc*4+1] = aN * u1;
        w_[dc*4+2] = aN * u2;
        w_[dc*4+3] = gN * u0 + zN * u3;
    }
#pragma unroll
    for (int dc = 0; dc < 4; dc++)
#pragma unroll
        for (int dt = 0; dt < 4; dt++)
            t[base + (dc << sc) + (dt << st)] = w_[dc * 4 + dt];
}

// ---------------------------------------------------------------------------
// Sim kernel: 256 blocks x 256 threads, 4096-elem smem tile, in-place.
// KIND 0: local slots {0..5};      fused passes cover M q0..q4 + CNOT chain
// KIND 1: local slots {0,1,2,6,7,8}; M q5..q8 + CNOT(q4..q8) chain
// KIND 2: local slots {0,1,2,3,4,9}; M q9 + CNOT(q8,q9), CNOT(q9,q0)
// ---------------------------------------------------------------------------
template<int KIND, bool INIT>
__global__ __launch_bounds__(256) void sim_kernel(const float* __restrict__ wts,
                                                  int layer) {
    __shared__ float t[4096];
    __shared__ float sM[10][16];
    unsigned blk = blockIdx.x, tid = threadIdx.x;

    auto gidx = [&](unsigned u) -> unsigned {
        if (KIND == 0)      return u | (blk << 12);
        else if (KIND == 1) return (u & 63u) | ((blk & 63u) << 6) |
                                   ((u >> 6) << 12) | ((blk >> 6) << 18);
        else                return (u & 1023u) | (blk << 10) | ((u >> 10) << 18);
    };

    if (INIT) {
        for (unsigned u = tid; u < 4096; u += 256) {
            unsigned p = gidx(u);
            t[u] = ((((p >> 1) ^ p) & 0x55555u) == 0u) ? 1.0f : 0.0f;
        }
    } else {
#pragma unroll
        for (int i = 0; i < 4; i++) {
            unsigned u = (tid + i * 256u) * 4u;
            *(float4*)&t[u] = *(const float4*)&g_c[gidx(u)];
        }
    }
    if (tid < 10) {
        int q = (int)tid;
        const float* a = wts + (layer * 10 + q) * 3;
        build_M(a[0], a[1], a[2], sM[q]);
    }
    __syncthreads();

    const float gamma = -expm1f(-1e-7f / 0.05f);
    const float gph   = -expm1f(-1e-7f / 0.07f);
    const float c2    = 1.0f - 4.0f * 0.01f / 3.0f;
    const float aN = sqrtf((1.f - gamma) * (1.f - gph)) * c2;
    const float zN = (1.f - gamma) * c2;
    const float gN = gamma;

    if (KIND == 0) {
        // q0->2 q1->3 q2->4 q3->5 q4->1
        pass<2, 3, true, true >(t, sM[1], sM[0], aN, zN, gN); __syncthreads(); // M0,M1,CNOT(q0,q1)
        pass<3, 4, true, false>(t, sM[2], 0,     aN, zN, gN); __syncthreads(); // M2, CNOT(q1,q2)
        pass<4, 5, true, false>(t, sM[3], 0,     aN, zN, gN); __syncthreads(); // M3, CNOT(q2,q3)
        pass<5, 1, true, false>(t, sM[4], 0,     aN, zN, gN); __syncthreads(); // M4, CNOT(q3,q4)
    } else if (KIND == 1) {
        // q4->1 q5->3 q6->4 q7->5 q8->0
        pass<1, 3, true, false>(t, sM[5], 0, aN, zN, gN); __syncthreads();     // M5, CNOT(q4,q5)
        pass<3, 4, true, false>(t, sM[6], 0, aN, zN, gN); __syncthreads();     // M6, CNOT(q5,q6)
        pass<4, 5, true, false>(t, sM[7], 0, aN, zN, gN); __syncthreads();     // M7, CNOT(q6,q7)
        pass<5, 0, true, false>(t, sM[8], 0, aN, zN, gN); __syncthreads();     // M8, CNOT(q7,q8)
    } else {
        // q8->0 q9->5 q0->2
        pass<0, 5, true,  false>(t, sM[9], 0, aN, zN, gN); __syncthreads();    // M9, CNOT(q8,q9)
        pass<5, 2, false, false>(t, 0,     0, aN, zN, gN); __syncthreads();    // CNOT(q9,q0)
    }

#pragma unroll
    for (int i = 0; i < 4; i++) {
        unsigned u = (tid + i * 256u) * 4u;
        *(float4*)&g_c[gidx(u)] = *(float4*)&t[u];
    }
}

// ---------------------------------------------------------------------------
// Logits: one block per batch row.
// ---------------------------------------------------------------------------
__global__ __launch_bounds__(256) void logits_kernel(
    const float* __restrict__ x, const float* __restrict__ bvec,
    const float* __restrict__ w, float* __restrict__ out) {
    __shared__ float xs[1024];
    __shared__ float cA[10], cB[10];
    __shared__ float red[8];
    int row = blockIdx.x, tid = threadIdx.x;

    for (int m = tid; m < 1024; m += 256)
        xs[m] = x[row * 1024 + m] + bvec[m];

    if (tid < 10) {
        const int slot_of_q[10] = {2, 3, 4, 5, 1, 6, 7, 8, 0, 9};
        int q = tid;
        int j = 9 - q;
        int s2 = 2 * slot_of_q[q];
        cA[j] = w[2 * q] * g_c[1u << s2];
        cB[j] = w[2 * q + 1] * 0.96f * g_c[3u << s2];   // readout: 1-2*0.02
    }
    __syncthreads();

    float acc = 0.f;
    for (int m = tid; m < 1024; m += 256) {
        float xm = xs[m];
        float s = 0.f;
#pragma unroll
        for (int j = 0; j < 10; j++) {
            s += cA[j] * xs[m ^ (1 << j)];
            s += cB[j] * (((m >> j) & 1) ? -xm : xm);
        }
        acc += xm * s;
    }
#pragma unroll
    for (int off = 16; off > 0; off >>= 1)
        acc += __shfl_down_sync(0xFFFFFFFFu, acc, off);
    if ((tid & 31) == 0) red[tid >> 5] = acc;
    __syncthreads();
    if (tid < 8) {
        float a = red[tid];
#pragma unroll
        for (int off = 4; off > 0; off >>= 1)
            a += __shfl_down_sync(0xFFu, a, off);
        if (tid == 0) out[row] = 1.f / (1.f + expf(-a));
    }
}

// ---------------------------------------------------------------------------
extern "C" void kernel_launch(void* const* d_in, const int* in_sizes, int n_in,
                              void* d_out, int out_size) {
    const float* x = nullptr;
    const float* bv = nullptr;
    const float* w = nullptr;
    const float* cw = nullptr;
    for (int i = 0; i < n_in; i++) {
        switch (in_sizes[i]) {
            case 2048 * 1024: x = (const float*)d_in[i]; break;
            case 1024:        bv = (const float*)d_in[i]; break;
            case 20:          w = (const float*)d_in[i]; break;
            case 90:          cw = (const float*)d_in[i]; break;
            default: break;  // P_tensor unused
        }
    }

    sim_kernel<0, true ><<<256, 256>>>(cw, 0);
    sim_kernel<1, false><<<256, 256>>>(cw, 0);
    sim_kernel<2, false><<<256, 256>>>(cw, 0);
    sim_kernel<0, false><<<256, 256>>>(cw, 1);
    sim_kernel<1, false><<<256, 256>>>(cw, 1);
    sim_kernel<2, false><<<256, 256>>>(cw, 1);
    sim_kernel<0, false><<<256, 256>>>(cw, 2);
    sim_kernel<1, false><<<256, 256>>>(cw, 2);
    sim_kernel<2, false><<<256, 256>>>(cw, 2);
    logits_kernel<<<2048, 256>>>(x, bv, w, (float*)d_out);
}

// round 5
// speedup vs baseline: 1.8167x; 1.2711x over previous
#include <cuda_runtime.h>
#include <math.h>

// ---------------------------------------------------------------------------
// NISQ classifier via Pauli-transfer-matrix simulation.
// State c[p], p = 10 base-4 digits (slots). Qubit -> slot:
//   q:    0  1  2  3  4  5  6  7  8  9
//   slot: 0  2  3  4  5  1  6  7  8  9
// Tile A (KIND 0): slots 0-5 local (bits 0-11)        -> CNOT 01,12,23,34,45
// Tile B (KIND 1): slots {0,1,6..9} (bits 0-3,12-19)  -> CNOT 56,67,78,89,90
// ---------------------------------------------------------------------------

#define NSTATE (1 << 20)
__device__ float g_c[NSTATE];   // PTM state vector (4 MB), logically indexed

// Bank swizzle: phys = u ^ SWf(u); SWf linear over u bits 5-8 -> bank bits 0-4.
// Conflict-free for every pass pattern below (verified algebraically).
__device__ __host__ constexpr unsigned SWf(unsigned u) {
    return ((((u >> 5) ^ (u >> 7)) & 1u))
         | ((((u >> 6)) & 1u) << 1)
         | ((((u >> 5) ^ (u >> 6)) & 1u) << 2)
         | ((((u >> 6) ^ (u >> 7)) & 1u) << 3)
         | ((((u >> 8)) & 1u) << 4);
}

// Build fused single-qubit PTM op: M = phase*amp*depol1*Rot (4x4, row I = e0)
__device__ __forceinline__ void build_M(float phi, float th, float om, float* M) {
    float cphi = cosf(phi), sphi = sinf(phi);
    float cth  = cosf(th),  sth  = sinf(th);
    float com  = cosf(om),  som  = sinf(om);
    float A[9]  = {com, -som, 0.f,  som, com, 0.f,  0.f, 0.f, 1.f};
    float Bm[9] = {cth, 0.f, sth,   0.f, 1.f, 0.f,  -sth, 0.f, cth};
    float C[9]  = {cphi, -sphi, 0.f, sphi, cphi, 0.f, 0.f, 0.f, 1.f};
    float AB[9], R[9];
#pragma unroll
    for (int i = 0; i < 3; i++)
#pragma unroll
        for (int j = 0; j < 3; j++) {
            float s = 0.f;
#pragma unroll
            for (int k = 0; k < 3; k++) s += A[i*3+k] * Bm[k*3+j];
            AB[i*3+j] = s;
        }
#pragma unroll
    for (int i = 0; i < 3; i++)
#pragma unroll
        for (int j = 0; j < 3; j++) {
            float s = 0.f;
#pragma unroll
            for (int k = 0; k < 3; k++) s += AB[i*3+k] * C[k*3+j];
            R[i*3+j] = s;
        }
    const float gamma = -expm1f(-1e-7f / 0.05f);
    const float gph   = -expm1f(-1e-7f / 0.07f);
    const float c1    = 1.0f - 4.0f * 0.001f / 3.0f;
    float sq = sqrtf((1.f - gamma) * (1.f - gph));
    float a1 = sq * c1, z1 = (1.f - gamma) * c1, g1 = gamma;
    M[0]  = 1.f; M[1]  = 0.f;       M[2]  = 0.f;       M[3]  = 0.f;
    M[4]  = 0.f; M[5]  = a1 * R[0]; M[6]  = a1 * R[1]; M[7]  = a1 * R[2];
    M[8]  = 0.f; M[9]  = a1 * R[3]; M[10] = a1 * R[4]; M[11] = a1 * R[5];
    M[12] = g1;  M[13] = z1 * R[6]; M[14] = z1 * R[7]; M[15] = z1 * R[8];
}

// Fused pass: (optional) single ops on control/target digits, CNOT signed
// permutation, then per-wire 2-qubit noise. One 16-elem group per thread.
template<int PC, int PT, bool HASMT, bool HASMC>
__device__ __forceinline__ void pass(float* t,
                                     const float* __restrict__ MT,
                                     const float* __restrict__ MC,
                                     float aN, float zN, float gN) {
    constexpr int sc = 2 * PC, st = 2 * PT;
    constexpr int plo  = (sc < st) ? sc : st;
    constexpr int phi_ = (sc < st) ? st : sc;
    constexpr int midw = phi_ - plo - 2;
    unsigned g    = threadIdx.x;                 // 256 groups, 256 threads
    unsigned lo   = g & ((1u << plo) - 1u);
    unsigned rest = g >> plo;
    unsigned mid  = rest & ((1u << midw) - 1u);
    unsigned hi   = rest >> midw;
    unsigned base = lo | (mid << (plo + 2)) | (hi << (phi_ + 2));
    unsigned pb   = base ^ SWf(base);            // swizzled base

    float v[16];
#pragma unroll
    for (int dc = 0; dc < 4; dc++)
#pragma unroll
        for (int dt = 0; dt < 4; dt++) {
            unsigned off = ((unsigned)dc << sc) | ((unsigned)dt << st);
            v[dc * 4 + dt] = t[pb ^ off ^ SWf(off)];   // XOR-immediate
        }

    if (HASMT) {   // single-qubit op on target digit
#pragma unroll
        for (int dc = 0; dc < 4; dc++) {
            float v0 = v[dc*4+0], v1 = v[dc*4+1], v2 = v[dc*4+2], v3 = v[dc*4+3];
            v[dc*4+1] = MT[5]  * v1 + MT[6]  * v2 + MT[7]  * v3;
            v[dc*4+2] = MT[9]  * v1 + MT[10] * v2 + MT[11] * v3;
            v[dc*4+3] = MT[12] * v0 + MT[13] * v1 + MT[14] * v2 + MT[15] * v3;
        }
    }
    if (HASMC) {   // single-qubit op on control digit
#pragma unroll
        for (int dt = 0; dt < 4; dt++) {
            float v0 = v[0+dt], v1 = v[4+dt], v2 = v[8+dt], v3 = v[12+dt];
            v[4 + dt]  = MC[5]  * v1 + MC[6]  * v2 + MC[7]  * v3;
            v[8 + dt]  = MC[9]  * v1 + MC[10] * v2 + MC[11] * v3;
            v[12 + dt] = MC[12] * v0 + MC[13] * v1 + MC[14] * v2 + MC[15] * v3;
        }
    }

    // CNOT PTM: out[i] = sgn[i] * in[tbl[i]], i = 4*control + target
    const int tbl[16] = {0, 1, 14, 15, 5, 4, 11, 10, 9, 8, 7, 6, 12, 13, 2, 3};
    float w_[16];
#pragma unroll
    for (int i = 0; i < 16; i++) w_[i] = v[tbl[i]];
    w_[7]  = -w_[7];
    w_[10] = -w_[10];
    // post-CNOT noise, control digit
#pragma unroll
    for (int dt = 0; dt < 4; dt++) {
        float u0 = w_[0+dt], u1 = w_[4+dt], u2 = w_[8+dt], u3 = w_[12+dt];
        w_[4 + dt]  = aN * u1;
        w_[8 + dt]  = aN * u2;
        w_[12 + dt] = gN * u0 + zN * u3;
    }
    // post-CNOT noise, target digit
#pragma unroll
    for (int dc = 0; dc < 4; dc++) {
        float u0 = w_[dc*4+0], u1 = w_[dc*4+1], u2 = w_[dc*4+2], u3 = w_[dc*4+3];
        w_[dc*4+1] = aN * u1;
        w_[dc*4+2] = aN * u2;
        w_[dc*4+3] = gN * u0 + zN * u3;
    }
#pragma unroll
    for (int dc = 0; dc < 4; dc++)
#pragma unroll
        for (int dt = 0; dt < 4; dt++) {
            unsigned off = ((unsigned)dc << sc) | ((unsigned)dt << st);
            t[pb ^ off ^ SWf(off)] = w_[dc * 4 + dt];
        }
}

// ---------------------------------------------------------------------------
// Sim kernel: 256 blocks x 256 threads, 4096-float swizzled smem tile.
// Global I/O is float4; smem side of the boundary copies is scalar (the
// swizzle breaks 16B smem alignment by design — banks need bits 0-4).
// ---------------------------------------------------------------------------
template<int KIND, bool INIT>
__global__ __launch_bounds__(256) void sim_kernel(const float* __restrict__ wts,
                                                  int layer) {
    __shared__ float t[4096];
    __shared__ float sM[10][16];
    unsigned blk = blockIdx.x, tid = threadIdx.x;

    auto gidx = [&](unsigned u) -> unsigned {
        if (KIND == 0) return u | (blk << 12);
        else           return (u & 15u) | (blk << 4) | ((u >> 4) << 12);
    };

    if (INIT) {
        for (unsigned u = tid; u < 4096; u += 256) {
            unsigned p = gidx(u);
            t[u ^ SWf(u)] = ((((p >> 1) ^ p) & 0x55555u) == 0u) ? 1.0f : 0.0f;
        }
    } else {
#pragma unroll
        for (int i = 0; i < 4; i++) {
            unsigned u = (tid + i * 256u) * 4u;
            float4 r = *(const float4*)&g_c[gidx(u)];
            unsigned sw = SWf(u);                 // same for u..u+3 (bits >=5)
            t[(u + 0) ^ sw] = r.x;
            t[(u + 1) ^ sw] = r.y;
            t[(u + 2) ^ sw] = r.z;
            t[(u + 3) ^ sw] = r.w;
        }
    }
    if (tid < 10) {
        int q = (int)tid;
        const float* a = wts + (layer * 10 + q) * 3;
        build_M(a[0], a[1], a[2], sM[q]);
    }
    __syncthreads();

    const float gamma = -expm1f(-1e-7f / 0.05f);
    const float gph   = -expm1f(-1e-7f / 0.07f);
    const float c2    = 1.0f - 4.0f * 0.01f / 3.0f;
    const float aN = sqrtf((1.f - gamma) * (1.f - gph)) * c2;
    const float zN = (1.f - gamma) * c2;
    const float gN = gamma;

    if (KIND == 0) {
        // local pos: q0->0 q5->1 q1->2 q2->3 q3->4 q4->5
        pass<0, 2, true, true >(t, sM[1], sM[0], aN, zN, gN); __syncthreads(); // M0,M1,CNOT(q0,q1)
        pass<2, 3, true, false>(t, sM[2], 0,     aN, zN, gN); __syncthreads(); // M2, CNOT(q1,q2)
        pass<3, 4, true, false>(t, sM[3], 0,     aN, zN, gN); __syncthreads(); // M3, CNOT(q2,q3)
        pass<4, 5, true, false>(t, sM[4], 0,     aN, zN, gN); __syncthreads(); // M4, CNOT(q3,q4)
        pass<5, 1, true, false>(t, sM[5], 0,     aN, zN, gN); __syncthreads(); // M5, CNOT(q4,q5)
    } else {
        // local pos: q0->0 q5->1 q6->2 q7->3 q8->4 q9->5
        pass<1, 2, true, false>(t, sM[6], 0, aN, zN, gN); __syncthreads();     // M6, CNOT(q5,q6)
        pass<2, 3, true, false>(t, sM[7], 0, aN, zN, gN); __syncthreads();     // M7, CNOT(q6,q7)
        pass<3, 4, true, false>(t, sM[8], 0, aN, zN, gN); __syncthreads();     // M8, CNOT(q7,q8)
        pass<4, 5, true, false>(t, sM[9], 0, aN, zN, gN); __syncthreads();     // M9, CNOT(q8,q9)
        pass<5, 0, false,false>(t, 0,     0, aN, zN, gN); __syncthreads();     // CNOT(q9,q0)
    }

#pragma unroll
    for (int i = 0; i < 4; i++) {
        unsigned u = (tid + i * 256u) * 4u;
        unsigned sw = SWf(u);
        float4 r;
        r.x = t[(u + 0) ^ sw];
        r.y = t[(u + 1) ^ sw];
        r.z = t[(u + 2) ^ sw];
        r.w = t[(u + 3) ^ sw];
        *(float4*)&g_c[gidx(u)] = r;
    }
}

// ---------------------------------------------------------------------------
// Logits: one block per batch row.
// ---------------------------------------------------------------------------
__global__ __launch_bounds__(256) void logits_kernel(
    const float* __restrict__ x, const float* __restrict__ bvec,
    const float* __restrict__ w, float* __restrict__ out) {
    __shared__ float xs[1024];
    __shared__ float cA[10], cB[10];
    __shared__ float red[8];
    int row = blockIdx.x, tid = threadIdx.x;

    for (int m = tid; m < 1024; m += 256)
        xs[m] = x[row * 1024 + m] + bvec[m];

    if (tid < 10) {
        const int slot_of_q[10] = {0, 2, 3, 4, 5, 1, 6, 7, 8, 9};
        int q = tid;
        int j = 9 - q;
        int s2 = 2 * slot_of_q[q];
        cA[j] = w[2 * q] * g_c[1u << s2];
        cB[j] = w[2 * q + 1] * 0.96f * g_c[3u << s2];   // readout: 1-2*0.02
    }
    __syncthreads();

    float acc = 0.f;
    for (int m = tid; m < 1024; m += 256) {
        float xm = xs[m];
        float s = 0.f;
#pragma unroll
        for (int j = 0; j < 10; j++) {
            s += cA[j] * xs[m ^ (1 << j)];
            s += cB[j] * (((m >> j) & 1) ? -xm : xm);
        }
        acc += xm * s;
    }
#pragma unroll
    for (int off = 16; off > 0; off >>= 1)
        acc += __shfl_down_sync(0xFFFFFFFFu, acc, off);
    if ((tid & 31) == 0) red[tid >> 5] = acc;
    __syncthreads();
    if (tid < 8) {
        float a = red[tid];
#pragma unroll
        for (int off = 4; off > 0; off >>= 1)
            a += __shfl_down_sync(0xFFu, a, off);
        if (tid == 0) out[row] = 1.f / (1.f + expf(-a));
    }
}

// ---------------------------------------------------------------------------
extern "C" void kernel_launch(void* const* d_in, const int* in_sizes, int n_in,
                              void* d_out, int out_size) {
    const float* x = nullptr;
    const float* bv = nullptr;
    const float* w = nullptr;
    const float* cw = nullptr;
    for (int i = 0; i < n_in; i++) {
        switch (in_sizes[i]) {
            case 2048 * 1024: x = (const float*)d_in[i]; break;
            case 1024:        bv = (const float*)d_in[i]; break;
            case 20:          w = (const float*)d_in[i]; break;
            case 90:          cw = (const float*)d_in[i]; break;
            default: break;  // P_tensor unused
        }
    }

    sim_kernel<0, true ><<<256, 256>>>(cw, 0);
    sim_kernel<1, false><<<256, 256>>>(cw, 0);
    sim_kernel<0, false><<<256, 256>>>(cw, 1);
    sim_kernel<1, false><<<256, 256>>>(cw, 1);
    sim_kernel<0, false><<<256, 256>>>(cw, 2);
    sim_kernel<1, false><<<256, 256>>>(cw, 2);
    logits_kernel<<<2048, 256>>>(x, bv, w, (float*)d_out);
}